// round 11
// baseline (speedup 1.0000x reference)
#include <cuda_runtime.h>

#define SEQ   512
#define BATCH 4096
#define HID   30
#define ROWF  48   // floats per (buf,b) row -> b0/b1 and warp halves bank-disjoint for LDS+STS
#define PF    4    // X prefetch depth

typedef unsigned long long ull;

__device__ __forceinline__ ull pk2(float a, float b) {
    ull r; asm("mov.b64 %0,{%1,%2};" : "=l"(r) : "f"(a), "f"(b)); return r;
}
__device__ __forceinline__ void unpk2(ull v, float& a, float& b) {
    asm("mov.b64 {%0,%1},%2;" : "=f"(a), "=f"(b) : "l"(v));
}
// Packed dual-fp32 FMA / ADD (Blackwell f32x2).
__device__ __forceinline__ ull ffma2(ull a, ull b, ull c) {
    ull d; asm("fma.rn.f32x2 %0,%1,%2,%3;" : "=l"(d) : "l"(a), "l"(b), "l"(c)); return d;
}
__device__ __forceinline__ ull add2(ull a, ull b) {
    ull d; asm("add.rn.f32x2 %0,%1,%2;" : "=l"(d) : "l"(a), "l"(b)); return d;
}

// tanh with PRE-SCALED input (2*log2e folded into weights): tanh = 1 - 2/(exp2(v)+1).
__device__ __forceinline__ float tanh_ps(float v) {
    float e, r;
    asm("ex2.approx.f32 %0, %1;" : "=f"(e) : "f"(v));
    asm("rcp.approx.f32 %0, %1;" : "=f"(r) : "f"(e + 1.0f));
    return fmaf(-2.0f, r, 1.0f);
}

__global__ void __launch_bounds__(64)
rnn_kernel(const float* __restrict__ X,     const float* __restrict__ W_ih,
           const float* __restrict__ W_hh,  const float* __restrict__ b_ih,
           const float* __restrict__ b_hh,  const float* __restrict__ W_out,
           const float* __restrict__ b_out, float* __restrict__ Y)
{
    // h double buffer, natural layout: hbuf[buf][b][k] = h[k]; k=30..47 stays 0.
    __shared__ __align__(16) float hbuf[2][2][ROWF];

    const int tid  = threadIdx.x;
    const int w    = tid >> 5;             // warp 0: units 0-14 (+y row); warp 1: units 15-29
    const int lane = tid & 31;
    const int r    = lane & 15;            // row within warp (15 = y-row on warp 0 / idle on warp 1)
    const int b    = lane >> 4;            // which of the CTA's 2 batches
    const int j    = 15 * w + r;           // hidden unit (valid for r<15)
    const bool hrow = (r < 15);
    const bool yrow = (w == 0) && (r == 15);
    const int batch = blockIdx.x * 2 + b;

    const float SC = 2.8853900817779268f;  // 2*log2(e), folded into pre-tanh weights

    // ---- this lane's row of the 31-row matrix, packed over (k even, k odd): 15 pairs ----
    ull wv[15];
#pragma unroll
    for (int i = 0; i < 15; i++) {
        const int k0 = 2 * i, k1 = 2 * i + 1;
        float a0 = 0.0f, a1 = 0.0f;
        if (hrow)      { a0 = SC * W_hh[j * HID + k0]; a1 = SC * W_hh[j * HID + k1]; }
        else if (yrow) { a0 = W_out[k0];               a1 = W_out[k1]; }
        wv[i] = pk2(a0, a1);
    }
    const float wih = hrow ? SC * W_ih[j] : 0.0f;
    const float bi  = hrow ? SC * (b_ih[j] + b_hh[j]) : (yrow ? b_out[0] : 0.0f);

    // ---- zero both buffers incl. pad ----
    for (int i = tid; i < 2 * 2 * ROWF; i += 64)
        (&hbuf[0][0][0])[i] = 0.0f;
    __syncthreads();

    const float* Xb = X + batch;
    float*       Yb = Y + batch;

    // ---- X prefetch ring (2 addresses/warp, one 128B line) ----
    float xbuf[PF];
#pragma unroll
    for (int i = 0; i < PF; i++) xbuf[i] = Xb[i * BATCH];

    for (int s0 = 0; s0 < SEQ; s0 += PF) {
        const float* Xpf = Xb + (s0 + PF) * BATCH;
        const bool more = (s0 + PF) < SEQ;

#pragma unroll
        for (int u = 0; u < PF; u++) {
            const int s = s0 + u;
            const float4* hc = (const float4*)&hbuf[s & 1][b][0];
            float*        hn = &hbuf[(s & 1) ^ 1][b][0];

            const float xc = xbuf[u];
            if (more) xbuf[u] = Xpf[u * BATCH];

            // ---- row matvec: 15 k-pairs (k=0..29), 4 split chains, 8 LDS.128 ----
            const float4 f0 = hc[0], f1 = hc[1], f2 = hc[2], f3 = hc[3];
            const float4 f4 = hc[4], f5 = hc[5], f6 = hc[6], f7 = hc[7];
            ull a0 = pk2(fmaf(wih, xc, bi), 0.0f), a1 = 0ull, a2 = 0ull, a3 = 0ull;
            a0 = ffma2(wv[0],  pk2(f0.x, f0.y), a0);
            a1 = ffma2(wv[1],  pk2(f0.z, f0.w), a1);
            a2 = ffma2(wv[2],  pk2(f1.x, f1.y), a2);
            a3 = ffma2(wv[3],  pk2(f1.z, f1.w), a3);
            a0 = ffma2(wv[4],  pk2(f2.x, f2.y), a0);
            a1 = ffma2(wv[5],  pk2(f2.z, f2.w), a1);
            a2 = ffma2(wv[6],  pk2(f3.x, f3.y), a2);
            a3 = ffma2(wv[7],  pk2(f3.z, f3.w), a3);
            a0 = ffma2(wv[8],  pk2(f4.x, f4.y), a0);
            a1 = ffma2(wv[9],  pk2(f4.z, f4.w), a1);
            a2 = ffma2(wv[10], pk2(f5.x, f5.y), a2);
            a3 = ffma2(wv[11], pk2(f5.z, f5.w), a3);
            a0 = ffma2(wv[12], pk2(f6.x, f6.y), a0);
            a1 = ffma2(wv[13], pk2(f6.z, f6.w), a1);
            a2 = ffma2(wv[14], pk2(f7.x, f7.y), a2);   // (h28,h29); f7.z/.w are zero pad

            const ull sum = add2(add2(a0, a1), add2(a2, a3));
            float v0, v1;
            unpk2(sum, v0, v1);
            const float v = v0 + v1;       // hrow: pre-tanh unit j ; yrow: y[s-1]

            // ---- y store (warp 0, lanes 15/31 — predicated, warp stays convergent) ----
            if (yrow && s > 0) Yb[(s - 1) * BATCH] = v;

            // ---- tanh + publish own unit ----
            const float h = tanh_ps(v);
            if (hrow) hn[j] = h;           // STS.32, bank-disjoint across warps & batches

            __syncthreads();               // one barrier/step: exchange halves (double-buffered)
        }
    }

    // ---- epilogue: y[SEQ-1] from final state (buffer 0, SEQ even) ----
    {
        const float4* hc = (const float4*)&hbuf[0][b][0];
        const float4 f0 = hc[0], f1 = hc[1], f2 = hc[2], f3 = hc[3];
        const float4 f4 = hc[4], f5 = hc[5], f6 = hc[6], f7 = hc[7];
        ull a0 = pk2(bi, 0.0f), a1 = 0ull;
        a0 = ffma2(wv[0],  pk2(f0.x, f0.y), a0); a1 = ffma2(wv[1],  pk2(f0.z, f0.w), a1);
        a0 = ffma2(wv[2],  pk2(f1.x, f1.y), a0); a1 = ffma2(wv[3],  pk2(f1.z, f1.w), a1);
        a0 = ffma2(wv[4],  pk2(f2.x, f2.y), a0); a1 = ffma2(wv[5],  pk2(f2.z, f2.w), a1);
        a0 = ffma2(wv[6],  pk2(f3.x, f3.y), a0); a1 = ffma2(wv[7],  pk2(f3.z, f3.w), a1);
        a0 = ffma2(wv[8],  pk2(f4.x, f4.y), a0); a1 = ffma2(wv[9],  pk2(f4.z, f4.w), a1);
        a0 = ffma2(wv[10], pk2(f5.x, f5.y), a0); a1 = ffma2(wv[11], pk2(f5.z, f5.w), a1);
        a0 = ffma2(wv[12], pk2(f6.x, f6.y), a0); a1 = ffma2(wv[13], pk2(f6.z, f6.w), a1);
        a0 = ffma2(wv[14], pk2(f7.x, f7.y), a0);
        const ull sum = add2(a0, a1);
        float v0, v1;
        unpk2(sum, v0, v1);
        if (yrow) Yb[(SEQ - 1) * BATCH] = v0 + v1;
    }
}

extern "C" void kernel_launch(void* const* d_in, const int* in_sizes, int n_in,
                              void* d_out, int out_size)
{
    (void)in_sizes; (void)n_in; (void)out_size;
    rnn_kernel<<<BATCH / 2, 64>>>(
        (const float*)d_in[0],  // X
        (const float*)d_in[1],  // W_ih
        (const float*)d_in[2],  // W_hh
        (const float*)d_in[3],  // b_ih
        (const float*)d_in[4],  // b_hh
        (const float*)d_in[5],  // W_out
        (const float*)d_in[6],  // b_out
        (float*)d_out);
}